// round 7
// baseline (speedup 1.0000x reference)
#include <cuda_runtime.h>

typedef unsigned long long u64;

#define HH    56
#define WW    56
#define CIN   64
#define COUT  64
#define TILE  8

__device__ __forceinline__ u64 addx2(u64 a, u64 b) {
    u64 r; asm("add.rn.f32x2 %0, %1, %2;" : "=l"(r) : "l"(a), "l"(b)); return r;
}
__device__ __forceinline__ u64 pack2(float lo, float hi) {
    u64 r; asm("mov.b64 %0, {%1, %2};" : "=l"(r) : "f"(lo), "f"(hi)); return r;
}
__device__ __forceinline__ void unpack2(u64 v, float& lo, float& hi) {
    asm("mov.b64 {%0, %1}, %2;" : "=f"(lo), "=f"(hi) : "l"(v));
}
__device__ __forceinline__ u64 abs2(u64 v) {  // 2x LOP3 (alu pipe)
    return v & 0x7FFFFFFF7FFFFFFFull;
}

// x pre-paired stride-4: sxp[ci][row][t] = (x[t], x[t+4]), t=0..5 (48B rows, 16B aligned)
__shared__ __align__(16) u64 sxp[8][10][6];
__shared__ __align__(16) u64 swd[8][9][32];   // dup (-w,-w) pairs

// CTA: one n, 8x8 tile, 32 output channels. 128 thr: py=tid&7, 2 channels/thread.
__global__ void __launch_bounds__(128, 5)
adder2d_kernel(const float* __restrict__ x,
               const float* __restrict__ w,
               float* __restrict__ out)
{
    const int tid  = threadIdx.x;
    const int py   = tid & 7;
    const int co2  = (tid >> 3) * 2;

    const int tx0    = blockIdx.x * TILE;
    const int ty0    = blockIdx.y * TILE;
    const int n      = blockIdx.z >> 1;
    const int cobase = (blockIdx.z & 1) * 32;

    const float* xn = x + (size_t)n * CIN * HH * WW;

    u64 acc[2][4];
    #pragma unroll
    for (int c = 0; c < 2; ++c)
        #pragma unroll
        for (int p = 0; p < 4; ++p) acc[c][p] = 0ull;

    // register ping-pong buffers for the (ci,kh) software pipeline
    u64        xr[2][6];
    ulonglong2 wr[2][3];

    for (int c8 = 0; c8 < 8; ++c8) {
        __syncthreads();   // previous chunk's readers done

        // ---- stage x chunk: 8 ci x 10 rows x 6 stride-4 pairs ----
        #pragma unroll
        for (int it = 0; it < 4; ++it) {
            int idx = it * 128 + tid;
            if (idx < 480) {
                int ci_l = idx / 60;
                int r    = idx - ci_l * 60;
                int row  = r / 6;
                int t    = r - row * 6;
                int gy   = ty0 + row - 1;
                int gx0  = tx0 + t - 1;
                float lo = 0.0f, hi = 0.0f;
                if ((unsigned)gy < (unsigned)HH) {
                    const float* base = &xn[((c8 * 8 + ci_l) * HH + gy) * WW];
                    if ((unsigned)gx0 < (unsigned)WW)       lo = base[gx0];
                    if ((unsigned)(gx0 + 4) < (unsigned)WW) hi = base[gx0 + 4];
                }
                sxp[ci_l][row][t] = pack2(lo, hi);
            }
        }
        // ---- stage weights: 8 ci x 9 k x 32 co, negated + duplicated ----
        #pragma unroll
        for (int it = 0; it < 18; ++it) {
            int idx  = it * 128 + tid;
            int co   = idx & 31;
            int rest = idx >> 5;
            int k    = rest % 9;
            int ci_l = rest / 9;
            float wv = -w[((cobase + co) * CIN + c8 * 8 + ci_l) * 9 + k];
            swd[ci_l][k][co] = pack2(wv, wv);
        }
        __syncthreads();

        // ---- load one (ci,kh) step into register buffer b ----
        auto load_step = [&](int b, int ci, int kh) {
            const ulonglong2* xp = (const ulonglong2*)&sxp[ci][py + kh][0];
            ulonglong2 a = xp[0], m = xp[1], e = xp[2];   // 3x LDS.128
            xr[b][0] = a.x; xr[b][1] = a.y;
            xr[b][2] = m.x; xr[b][3] = m.y;
            xr[b][4] = e.x; xr[b][5] = e.y;
            wr[b][0] = *(const ulonglong2*)&swd[ci][kh * 3 + 0][co2];
            wr[b][1] = *(const ulonglong2*)&swd[ci][kh * 3 + 1][co2];
            wr[b][2] = *(const ulonglong2*)&swd[ci][kh * 3 + 2][co2];
        };
        auto compute_step = [&](int b) {
            #pragma unroll
            for (int kw = 0; kw < 3; ++kw) {
                u64 p0 = xr[b][kw], p1 = xr[b][kw + 1],
                    p2 = xr[b][kw + 2], p3 = xr[b][kw + 3];
                ulonglong2 wp = wr[b][kw];
                acc[0][0] = addx2(acc[0][0], abs2(addx2(p0, wp.x)));
                acc[0][1] = addx2(acc[0][1], abs2(addx2(p1, wp.x)));
                acc[0][2] = addx2(acc[0][2], abs2(addx2(p2, wp.x)));
                acc[0][3] = addx2(acc[0][3], abs2(addx2(p3, wp.x)));
                acc[1][0] = addx2(acc[1][0], abs2(addx2(p0, wp.y)));
                acc[1][1] = addx2(acc[1][1], abs2(addx2(p1, wp.y)));
                acc[1][2] = addx2(acc[1][2], abs2(addx2(p2, wp.y)));
                acc[1][3] = addx2(acc[1][3], abs2(addx2(p3, wp.y)));
            }
        };

        // ---- 24-step software pipeline: load s+1 while computing s ----
        load_step(0, 0, 0);
        #pragma unroll 2
        for (int ci = 0; ci < 8; ++ci) {
            #pragma unroll
            for (int kh = 0; kh < 3; ++kh) {
                const int s  = ci * 3 + kh;          // compile-time parity after unroll
                const int b  = s & 1;
                int ns = s + 1; if (ns > 23) ns = 23;   // last step: harmless reload
                load_step(b ^ 1, ns / 3, ns % 3);
                compute_step(b);
            }
        }
    }

    // ---- epilogue: acc[c][j] holds output pixels (j, j+4) ----
    #pragma unroll
    for (int c = 0; c < 2; ++c) {
        float f[8];
        #pragma unroll
        for (int j = 0; j < 4; ++j) {
            float lo, hi;
            unpack2(acc[c][j], lo, hi);
            f[j]     = -lo;
            f[j + 4] = -hi;
        }
        float* o = out + (((size_t)n * COUT + cobase + co2 + c) * HH + (ty0 + py)) * WW + tx0;
        ((float4*)o)[0] = make_float4(f[0], f[1], f[2], f[3]);
        ((float4*)o)[1] = make_float4(f[4], f[5], f[6], f[7]);
    }
}

extern "C" void kernel_launch(void* const* d_in, const int* in_sizes, int n_in,
                              void* d_out, int out_size)
{
    const float* x = (const float*)d_in[0];
    const float* w = (const float*)d_in[1];
    float* out     = (float*)d_out;

    dim3 grid(WW / TILE, HH / TILE, 32);   // 1568 CTAs
    adder2d_kernel<<<grid, 128>>>(x, w, out);
}